// round 12
// baseline (speedup 1.0000x reference)
#include <cuda_runtime.h>
#include <cuda_fp16.h>
#include <math.h>
#include <stdint.h>

// ---------------------------------------------------------------------------
// ResamplerSD3: 8-layer Perceiver resampler.
// fp16 mma.sync (m16n8k16) GEMMs w/ fp32 accum, cp.async.bulk fills,
// occupancy-tuned tiles (128x128 @2 CTA/SM, 64x128 @3 CTA/SM).
// ---------------------------------------------------------------------------

#define Bb   32
#define N1   257
#define EMB  768
#define DIM  1024
#define HEADS 16
#define DH   64
#define NQ   64
#define FFI  4096
#define NK   (N1 + NQ)        // 321
#define DEPTH 8

#define STG  4
#define BKT  32               // K per stage (32 fp16 = 64B per row)
#define AS_H 40               // smem row stride in halves (64B data + 16B pad)

// ---------------- static device scratch (no allocations allowed) -----------
__device__ float  g_xf   [Bb * N1 * DIM];
__device__ float  g_lat  [Bb * NQ * DIM];
__device__ float  g_q    [Bb * NQ * DIM];
__device__ float  g_kv   [Bb * NK * 2 * DIM];
__device__ float  g_tmp  [Bb * NQ * DIM];
__device__ __half g_x16  [Bb * N1 * EMB];
__device__ __half g_cat16[Bb * NK * DIM];
__device__ __half g_ll16 [Bb * NQ * DIM];
__device__ __half g_o16  [Bb * NQ * DIM];
__device__ __half g_h16  [Bb * NQ * FFI];
__device__ __half g_lat16[Bb * NQ * DIM];
__device__ __half g_wt16 [102498304];        // all weights, transposed [N][K] fp16

#define OFF_PIN  0
#define OFF_WQ   (OFF_PIN + 768 * 1024)
#define OFF_WKV  (OFF_WQ  + 8 * 1024 * 1024)
#define OFF_WO   (OFF_WKV + 8 * 1024 * 2048)
#define OFF_W1   (OFF_WO  + 8 * 1024 * 1024)
#define OFF_W2   (OFF_W1  + 8 * 1024 * 4096)
#define OFF_POUT (OFF_W2  + 8 * 4096 * 1024)

// ---------------------------------------------------------------------------
__device__ __forceinline__ void mma_f16(float* d, const uint32_t* a, const uint32_t* b)
{
    asm volatile(
        "mma.sync.aligned.m16n8k16.row.col.f32.f16.f16.f32 "
        "{%0,%1,%2,%3}, {%4,%5,%6,%7}, {%8,%9}, {%0,%1,%2,%3};\n"
        : "+f"(d[0]), "+f"(d[1]), "+f"(d[2]), "+f"(d[3])
        : "r"(a[0]), "r"(a[1]), "r"(a[2]), "r"(a[3]), "r"(b[0]), "r"(b[1]));
}

__device__ __forceinline__ void mbar_init(uint32_t a, uint32_t cnt)
{
    asm volatile("mbarrier.init.shared.b64 [%0], %1;" :: "r"(a), "r"(cnt) : "memory");
}
__device__ __forceinline__ void mbar_expect_tx(uint32_t a, uint32_t bytes)
{
    asm volatile("mbarrier.arrive.expect_tx.shared.b64 _, [%0], %1;"
                 :: "r"(a), "r"(bytes) : "memory");
}
__device__ __forceinline__ void mbar_wait(uint32_t a, uint32_t parity)
{
    asm volatile(
        "{\n\t.reg .pred P;\n\t"
        "LW%=:\n\t"
        "mbarrier.try_wait.parity.acquire.cta.shared::cta.b64 P, [%0], %1, 0x989680;\n\t"
        "@!P bra LW%=;\n\t"
        "}" :: "r"(a), "r"(parity) : "memory");
}
__device__ __forceinline__ void bulk_g2s(uint32_t dst, const void* src,
                                         uint32_t bytes, uint32_t mbar)
{
    asm volatile(
        "cp.async.bulk.shared::cluster.global.mbarrier::complete_tx::bytes "
        "[%0], [%1], %2, [%3];"
        :: "r"(dst), "l"(src), "r"(bytes), "r"(mbar) : "memory");
}

// ---------------------------------------------------------------------------
// fp16 GEMM: C[M,N] = A[M,K](fp16) @ Bt[N,K](fp16)^T (+bias)(gelu)(+res).
// fp32 accumulate. Warp tile 32x64, NWM x NWN warps. K % 32 == 0,
// N % (NWN*64) == 0. M guarded. Output fp32 or fp16 (out_half).
// ---------------------------------------------------------------------------
template<int NWM, int NWN, int MINB>
__global__ void __launch_bounds__(NWM * NWN * 32, MINB)
hgemm(int M, int N, int K,
      const __half* __restrict__ A, const __half* __restrict__ Bt,
      void* __restrict__ Cv, const float* __restrict__ bias,
      const float* __restrict__ res, int do_gelu, int out_half)
{
    constexpr int BM = NWM * 32;
    constexpr int BN = NWN * 64;
    constexpr int NT = NWM * NWN * 32;
    constexpr int A_SB = BM * AS_H * 2;
    constexpr int B_SB = BN * AS_H * 2;
    constexpr int STAGE_B = A_SB + B_SB;
    constexpr int KTB = (BM + BN) * 64;

    extern __shared__ char smraw[];
    const uint32_t sb = (uint32_t)__cvta_generic_to_shared(smraw);
    const uint32_t sd = sb + 64;

    const int tid  = threadIdx.x;
    const int wid  = tid >> 5;
    const int lane = tid & 31;
    const int gid  = lane >> 2;
    const int tig  = lane & 3;
    const int bx   = blockIdx.x;
    const int by   = blockIdx.y;

    const int warp_m = (wid % NWM) * 32;
    const int warp_n = (wid / NWM) * 64;

    if (tid == 0) {
#pragma unroll
        for (int s = 0; s < STG; s++) mbar_init(sb + 8 * s, 1);
    }
    __syncthreads();

    const int nk = K / BKT;

    auto fill = [&](int slot, int kt) {
        const uint32_t base = sd + (uint32_t)slot * STAGE_B;
        const uint32_t mbar = sb + 8 * slot;
        if (tid == 0) mbar_expect_tx(mbar, KTB);
        for (int idx = tid; idx < BM + BN; idx += NT) {
            if (idx < BM) {
                int grow = by * BM + idx;
                const __half* src = A + (size_t)(grow < M ? grow : 0) * K + kt * BKT;
                bulk_g2s(base + (uint32_t)idx * (AS_H * 2), src, 64, mbar);
            } else {
                int r = idx - BM;
                const __half* src = Bt + (size_t)(bx * BN + r) * K + kt * BKT;
                bulk_g2s(base + A_SB + (uint32_t)r * (AS_H * 2), src, 64, mbar);
            }
        }
    };

    float acc[2][8][4];
#pragma unroll
    for (int mm = 0; mm < 2; mm++)
#pragma unroll
        for (int nn = 0; nn < 8; nn++)
#pragma unroll
            for (int r = 0; r < 4; r++) acc[mm][nn][r] = 0.0f;

#pragma unroll
    for (int s = 0; s < STG; s++)
        if (s < nk) fill(s, s);

    for (int kt = 0; kt < nk; kt++) {
        const int slot = kt % STG;
        const uint32_t parity = ((uint32_t)(kt / STG)) & 1u;
        mbar_wait(sb + 8 * slot, parity);

        const uint32_t* As32 = (const uint32_t*)(smraw + 64 + (size_t)slot * STAGE_B);
        const uint32_t* Bs32 = As32 + A_SB / 4;

#pragma unroll
        for (int ks = 0; ks < 2; ks++) {
            const int kb2 = ks * 8;   // u32 offset within row (16 halves)
            uint32_t a[2][4], b[8][2];
#pragma unroll
            for (int mm = 0; mm < 2; mm++) {
                int r0 = warp_m + mm * 16 + gid;
                a[mm][0] = As32[r0 * 20 + kb2 + tig];
                a[mm][1] = As32[(r0 + 8) * 20 + kb2 + tig];
                a[mm][2] = As32[r0 * 20 + kb2 + tig + 4];
                a[mm][3] = As32[(r0 + 8) * 20 + kb2 + tig + 4];
            }
#pragma unroll
            for (int nn = 0; nn < 8; nn++) {
                int c0 = warp_n + nn * 8 + gid;
                b[nn][0] = Bs32[c0 * 20 + kb2 + tig];
                b[nn][1] = Bs32[c0 * 20 + kb2 + tig + 4];
            }
#pragma unroll
            for (int mm = 0; mm < 2; mm++)
#pragma unroll
                for (int nn = 0; nn < 8; nn++)
                    mma_f16(acc[mm][nn], a[mm], b[nn]);
        }

        __syncthreads();
        if (kt + STG < nk) {
            asm volatile("fence.proxy.async.shared::cta;" ::: "memory");
            fill(slot, kt + STG);
        }
    }

    // ---- epilogue ----
    float* Cf = (float*)Cv;
    __half* Ch = (__half*)Cv;
#pragma unroll
    for (int mm = 0; mm < 2; mm++) {
#pragma unroll
        for (int hf = 0; hf < 2; hf++) {
            int row = by * BM + warp_m + mm * 16 + gid + hf * 8;
            if (row >= M) continue;
#pragma unroll
            for (int nn = 0; nn < 8; nn++) {
                int col = bx * BN + warp_n + nn * 8 + tig * 2;
                float v0 = acc[mm][nn][hf * 2 + 0];
                float v1 = acc[mm][nn][hf * 2 + 1];
                if (bias) { v0 += bias[col]; v1 += bias[col + 1]; }
                if (do_gelu) {
                    v0 = 0.5f * v0 * (1.0f + erff(v0 * 0.70710678118654752f));
                    v1 = 0.5f * v1 * (1.0f + erff(v1 * 0.70710678118654752f));
                }
                if (res) {
                    v0 += res[(size_t)row * N + col];
                    v1 += res[(size_t)row * N + col + 1];
                }
                if (out_half) {
                    *(__half2*)(Ch + (size_t)row * N + col) = __floats2half2_rn(v0, v1);
                } else {
                    Cf[(size_t)row * N + col]     = v0;
                    Cf[(size_t)row * N + col + 1] = v1;
                }
            }
        }
    }
}

#define SMEM_MID   (64 + STG * (128 * AS_H * 2 + 128 * AS_H * 2))   // 81984
#define SMEM_SMALL (64 + STG * (64  * AS_H * 2 + 128 * AS_H * 2))   // 61504

// ---------------------------------------------------------------------------
// Weight prep: transpose [K,N] fp32 -> [N,K] fp16. Grid z = layer.
// ---------------------------------------------------------------------------
__global__ void transpose_h(const float* __restrict__ in, __half* __restrict__ out,
                            int K, int N)
{
    __shared__ float t[32][33];
    in  += (size_t)blockIdx.z * K * N;
    out += (size_t)blockIdx.z * K * N;
    int x = blockIdx.x * 32 + threadIdx.x;
    int y0 = blockIdx.y * 32;
#pragma unroll
    for (int j = threadIdx.y; j < 32; j += 8)
        t[j][threadIdx.x] = in[(size_t)(y0 + j) * N + x];
    __syncthreads();
    int n0 = blockIdx.x * 32;
#pragma unroll
    for (int j = threadIdx.y; j < 32; j += 8)
        out[(size_t)(n0 + j) * K + y0 + threadIdx.x] = __float2half_rn(t[threadIdx.x][j]);
}

__global__ void tohalf_kernel(const float* __restrict__ in, __half* __restrict__ out,
                              int n4)
{
    int i = blockIdx.x * blockDim.x + threadIdx.x;
    if (i < n4) {
        float4 v = ((const float4*)in)[i];
        __half2* o = (__half2*)out + i * 2;
        o[0] = __floats2half2_rn(v.x, v.y);
        o[1] = __floats2half2_rn(v.z, v.w);
    }
}

// ---------------------------------------------------------------------------
__device__ __forceinline__ float2 block_reduce2(float a, float b)
{
    __shared__ float sa[8], sb_[8];
#pragma unroll
    for (int off = 16; off; off >>= 1) {
        a += __shfl_down_sync(0xFFFFFFFFu, a, off);
        b += __shfl_down_sync(0xFFFFFFFFu, b, off);
    }
    int w = threadIdx.x >> 5, l = threadIdx.x & 31;
    if (l == 0) { sa[w] = a; sb_[w] = b; }
    __syncthreads();
    if (w == 0) {
        a = (l < 8) ? sa[l] : 0.f;
        b = (l < 8) ? sb_[l] : 0.f;
#pragma unroll
        for (int off = 4; off; off >>= 1) {
            a += __shfl_down_sync(0xFFFFFFFFu, a, off);
            b += __shfl_down_sync(0xFFFFFFFFu, b, off);
        }
        if (l == 0) { sa[0] = a; sb_[0] = b; }
    }
    __syncthreads();
    return make_float2(sa[0], sb_[0]);
}

// LayerNorm width=1024. out/out2 fp16 when out_half, else fp32.
__global__ __launch_bounds__(256)
void ln_kernel(const float* __restrict__ in, void* __restrict__ out,
               void* __restrict__ out2,
               const float* __restrict__ g, const float* __restrict__ bta,
               int width, int rpb_in, int rpb_out, int out_off, int out_half)
{
    int row = blockIdx.x;
    const float* x = in + (size_t)row * width;
    int bi = row / rpb_in, n = row % rpb_in;
    size_t orow = (size_t)bi * rpb_out + out_off + n;

    float s = 0.f, s2 = 0.f;
    for (int i = threadIdx.x * 4; i < width; i += blockDim.x * 4) {
        float4 v = *(const float4*)(x + i);
        s  += v.x + v.y + v.z + v.w;
        s2 += v.x * v.x + v.y * v.y + v.z * v.z + v.w * v.w;
    }
    float2 r = block_reduce2(s, s2);
    float mean = r.x / (float)width;
    float var  = r.y / (float)width - mean * mean;
    float rstd = rsqrtf(var + 1e-5f);

    for (int i = threadIdx.x * 4; i < width; i += blockDim.x * 4) {
        float4 v = *(const float4*)(x + i);
        float4 gg = *(const float4*)(g + i);
        float4 bb = *(const float4*)(bta + i);
        float4 o;
        o.x = (v.x - mean) * rstd * gg.x + bb.x;
        o.y = (v.y - mean) * rstd * gg.y + bb.y;
        o.z = (v.z - mean) * rstd * gg.z + bb.z;
        o.w = (v.w - mean) * rstd * gg.w + bb.w;
        if (out_half) {
            __half2* y = (__half2*)((__half*)out + orow * width + i);
            y[0] = __floats2half2_rn(o.x, o.y);
            y[1] = __floats2half2_rn(o.z, o.w);
            if (out2) {
                __half2* y2 = (__half2*)((__half*)out2 + (size_t)row * width + i);
                y2[0] = __floats2half2_rn(o.x, o.y);
                y2[1] = __floats2half2_rn(o.z, o.w);
            }
        } else {
            *(float4*)((float*)out + orow * width + i) = o;
        }
    }
}

__global__ void bcast_kernel(const float* __restrict__ latents, float* __restrict__ lat)
{
    size_t i = (size_t)blockIdx.x * blockDim.x + threadIdx.x;
    size_t tot = (size_t)Bb * NQ * DIM;
    if (i < tot) lat[i] = latents[i % ((size_t)NQ * DIM)];
}

// ---------------------------------------------------------------------------
// Attention: per block (b, h, q-tile of 16 rows). fp32 math, fp16 output.
// ---------------------------------------------------------------------------
__global__ __launch_bounds__(256)
void attn_kernel(const float* __restrict__ q,
                 const float* __restrict__ kv,
                 __half* __restrict__ o)
{
    __shared__ float qs[16][DH];
    __shared__ float sc[16][NK];

    int blk = blockIdx.x;
    int qt = blk & 3;
    int h  = (blk >> 2) & 15;
    int b  = blk >> 6;

    const float* qbase = q + ((size_t)b * NQ + qt * 16) * DIM + h * DH;
    for (int i = threadIdx.x; i < 16 * DH; i += 256) {
        int r = i >> 6, c = i & 63;
        qs[r][c] = qbase[(size_t)r * DIM + c];
    }
    __syncthreads();

    const float* kbase = kv + (size_t)b * NK * (2 * DIM) + h * DH;
    const float* vbase = kbase + DIM;

    for (int idx = threadIdx.x; idx < 16 * NK; idx += 256) {
        int r = idx / NK, kk = idx % NK;
        const float* krow = kbase + (size_t)kk * (2 * DIM);
        float acc = 0.f;
#pragma unroll
        for (int d = 0; d < DH; d += 4) {
            float4 k4 = *(const float4*)(krow + d);
            acc += qs[r][d] * k4.x + qs[r][d + 1] * k4.y
                 + qs[r][d + 2] * k4.z + qs[r][d + 3] * k4.w;
        }
        sc[r][kk] = acc * 0.125f;
    }
    __syncthreads();

    int warp = threadIdx.x >> 5, lane = threadIdx.x & 31;
    for (int r = warp * 2; r < warp * 2 + 2; r++) {
        float mx = -1e30f;
        for (int k = lane; k < NK; k += 32) mx = fmaxf(mx, sc[r][k]);
#pragma unroll
        for (int off = 16; off; off >>= 1)
            mx = fmaxf(mx, __shfl_xor_sync(0xFFFFFFFFu, mx, off));
        float sum = 0.f;
        for (int k = lane; k < NK; k += 32) {
            float e = __expf(sc[r][k] - mx);
            sc[r][k] = e;
            sum += e;
        }
#pragma unroll
        for (int off = 16; off; off >>= 1)
            sum += __shfl_xor_sync(0xFFFFFFFFu, sum, off);
        float inv = 1.0f / sum;
        for (int k = lane; k < NK; k += 32) sc[r][k] *= inv;
    }
    __syncthreads();

    int d = threadIdx.x & 63;
    int r0 = threadIdx.x >> 6;
    float acc[4] = {0.f, 0.f, 0.f, 0.f};
    for (int k = 0; k < NK; k++) {
        float vv = vbase[(size_t)k * (2 * DIM) + d];
#pragma unroll
        for (int j = 0; j < 4; j++)
            acc[j] = fmaf(sc[r0 + 4 * j][k], vv, acc[j]);
    }
    __half* obase = o + ((size_t)b * NQ + qt * 16) * DIM + h * DH;
#pragma unroll
    for (int j = 0; j < 4; j++)
        obase[(size_t)(r0 + 4 * j) * DIM + d] = __float2half_rn(acc[j]);
}

// ---------------------------------------------------------------------------
static inline void gemm_mid(const __half* A, const __half* Bt, void* C,
                            int M, int N, int K,
                            const float* bias, const float* res, int gelu, int oh)
{
    dim3 grid(N / 128, (M + 127) / 128);
    hgemm<4, 2, 2><<<grid, 256, SMEM_MID>>>(M, N, K, A, Bt, C, bias, res, gelu, oh);
}
static inline void gemm_small(const __half* A, const __half* Bt, void* C,
                              int M, int N, int K,
                              const float* bias, const float* res, int gelu, int oh)
{
    dim3 grid(N / 128, (M + 63) / 64);
    hgemm<2, 2, 3><<<grid, 128, SMEM_SMALL>>>(M, N, K, A, Bt, C, bias, res, gelu, oh);
}

extern "C" void kernel_launch(void* const* d_in, const int* in_sizes, int n_in,
                              void* d_out, int out_size)
{
    const float* x          = (const float*)d_in[0];
    const float* latents    = (const float*)d_in[1];
    const float* proj_in_w  = (const float*)d_in[2];
    const float* proj_in_b  = (const float*)d_in[3];
    const float* ln1_g      = (const float*)d_in[4];
    const float* ln1_b      = (const float*)d_in[5];
    const float* ln2_g      = (const float*)d_in[6];
    const float* ln2_b      = (const float*)d_in[7];
    const float* Wq         = (const float*)d_in[8];
    const float* Wkv        = (const float*)d_in[9];
    const float* Wo         = (const float*)d_in[10];
    const float* ff_ln_g    = (const float*)d_in[11];
    const float* ff_ln_b    = (const float*)d_in[12];
    const float* ff_w1      = (const float*)d_in[13];
    const float* ff_w2      = (const float*)d_in[14];
    const float* proj_out_w = (const float*)d_in[15];
    const float* proj_out_b = (const float*)d_in[16];
    const float* norm_out_g = (const float*)d_in[17];
    const float* norm_out_b = (const float*)d_in[18];
    float* out = (float*)d_out;

    cudaFuncSetAttribute((const void*)hgemm<4, 2, 2>,
                         cudaFuncAttributeMaxDynamicSharedMemorySize, SMEM_MID);
    cudaFuncSetAttribute((const void*)hgemm<2, 2, 3>,
                         cudaFuncAttributeMaxDynamicSharedMemorySize, SMEM_SMALL);

    float  *xf, *lat, *qb, *kvb, *tmp;
    __half *x16, *cat16, *ll16, *o16, *h16, *lat16, *wt;
    cudaGetSymbolAddress((void**)&xf,    g_xf);
    cudaGetSymbolAddress((void**)&lat,   g_lat);
    cudaGetSymbolAddress((void**)&qb,    g_q);
    cudaGetSymbolAddress((void**)&kvb,   g_kv);
    cudaGetSymbolAddress((void**)&tmp,   g_tmp);
    cudaGetSymbolAddress((void**)&x16,   g_x16);
    cudaGetSymbolAddress((void**)&cat16, g_cat16);
    cudaGetSymbolAddress((void**)&ll16,  g_ll16);
    cudaGetSymbolAddress((void**)&o16,   g_o16);
    cudaGetSymbolAddress((void**)&h16,   g_h16);
    cudaGetSymbolAddress((void**)&lat16, g_lat16);
    cudaGetSymbolAddress((void**)&wt,    g_wt16);

    const int Mx = Bb * N1;   // 8224
    const int Ml = Bb * NQ;   // 2048
    const int Mc = Bb * NK;   // 10272

    // ---- prep ----
    {
        int n4 = Bb * N1 * EMB / 4;                                     // #0
        tohalf_kernel<<<(n4 + 255) / 256, 256>>>(x, x16, n4);
        size_t tot = (size_t)Bb * NQ * DIM;                             // #1
        bcast_kernel<<<(int)((tot + 255) / 256), 256>>>(latents, lat);
        transpose_h<<<dim3(DIM / 32, EMB / 32, 1), dim3(32, 8)>>>(      // #2
            proj_in_w, wt + OFF_PIN, EMB, DIM);
    }

    // #3: proj_in GEMM
    gemm_mid(x16, wt + OFF_PIN, xf, Mx, DIM, EMB, proj_in_b, nullptr, 0, 0);

    // remaining weight transposes
    transpose_h<<<dim3(DIM / 32, DIM / 32, DEPTH), dim3(32, 8)>>>(Wq, wt + OFF_WQ, DIM, DIM);
    transpose_h<<<dim3(2 * DIM / 32, DIM / 32, DEPTH), dim3(32, 8)>>>(Wkv, wt + OFF_WKV, DIM, 2 * DIM);
    transpose_h<<<dim3(DIM / 32, DIM / 32, DEPTH), dim3(32, 8)>>>(Wo, wt + OFF_WO, DIM, DIM);
    transpose_h<<<dim3(FFI / 32, DIM / 32, DEPTH), dim3(32, 8)>>>(ff_w1, wt + OFF_W1, DIM, FFI);
    transpose_h<<<dim3(DIM / 32, FFI / 32, DEPTH), dim3(32, 8)>>>(ff_w2, wt + OFF_W2, FFI, DIM);
    transpose_h<<<dim3(DIM / 32, DIM / 32, 1), dim3(32, 8)>>>(proj_out_w, wt + OFF_POUT, DIM, DIM);

    for (int i = 0; i < DEPTH; i++) {
        const __half* wq  = wt + OFF_WQ  + (size_t)i * DIM * DIM;
        const __half* wkv = wt + OFF_WKV + (size_t)i * DIM * 2 * DIM;
        const __half* wo  = wt + OFF_WO  + (size_t)i * DIM * DIM;
        const __half* w1  = wt + OFF_W1  + (size_t)i * DIM * FFI;
        const __half* w2  = wt + OFF_W2  + (size_t)i * FFI * DIM;

        // ln(xf) -> cat16 rows [0,257) per batch
        ln_kernel<<<Mx, 256>>>(xf, cat16, nullptr,
                               ln1_g + (size_t)i * DIM, ln1_b + (size_t)i * DIM,
                               DIM, N1, NK, 0, 1);
        // ln(lat) -> cat16 rows [257,321) AND ll16
        ln_kernel<<<Ml, 256>>>(lat, cat16, ll16,
                               ln2_g + (size_t)i * DIM, ln2_b + (size_t)i * DIM,
                               DIM, NQ, NK, N1, 1);

        gemm_small(ll16, wq, qb, Ml, DIM, DIM, nullptr, nullptr, 0, 0);     // q fp32
        gemm_mid(cat16, wkv, kvb, Mc, 2 * DIM, DIM, nullptr, nullptr, 0, 0);// kv fp32

        attn_kernel<<<Bb * HEADS * 4, 256>>>(qb, kvb, o16);                 // ob fp16

        gemm_small(o16, wo, lat, Ml, DIM, DIM, nullptr, lat, 0, 0);         // lat += o@Wo

        ln_kernel<<<Ml, 256>>>(lat, ll16, nullptr,
                               ff_ln_g + (size_t)i * DIM, ff_ln_b + (size_t)i * DIM,
                               DIM, NQ, NQ, 0, 1);
        gemm_mid(ll16, w1, h16, Ml, FFI, DIM, nullptr, nullptr, 1, 1);      // gelu, fp16
        gemm_small(h16, w2, lat, Ml, DIM, FFI, nullptr, lat, 0, 0);         // lat += h@W2
    }

    {
        int n4 = Bb * NQ * DIM / 4;
        tohalf_kernel<<<(n4 + 255) / 256, 256>>>(lat, lat16, n4);
    }
    gemm_small(lat16, wt + OFF_POUT, tmp, Ml, DIM, DIM, proj_out_b, nullptr, 0, 0);
    ln_kernel<<<Ml, 256>>>(tmp, out, nullptr, norm_out_g, norm_out_b, DIM, NQ, NQ, 0, 0);
}

// round 13
// speedup vs baseline: 1.4864x; 1.4864x over previous
#include <cuda_runtime.h>
#include <cuda_fp16.h>
#include <math.h>
#include <stdint.h>

// ---------------------------------------------------------------------------
// ResamplerSD3: 8-layer Perceiver resampler.
// fp16 mma.sync (m16n8k16) GEMMs, fp32 accum. Operands pre-packed into
// stage-contiguous swizzled tiles -> 2 cp.async.bulk per pipeline stage.
// ---------------------------------------------------------------------------

#define Bb   32
#define N1   257
#define EMB  768
#define DIM  1024
#define HEADS 16
#define DH   64
#define NQ   64
#define FFI  4096
#define NK   (N1 + NQ)        // 321
#define DEPTH 8

#define STG  3
#define BKT  64               // K per stage (64 halves = 128B per packed row)

// ---------------- static device scratch (no allocations allowed) -----------
__device__ float  g_xf   [Bb * N1 * DIM];
__device__ float  g_lat  [Bb * NQ * DIM];
__device__ float  g_q    [Bb * NQ * DIM];
__device__ float  g_kv   [Bb * NK * 2 * DIM];
__device__ float  g_tmp  [Bb * NQ * DIM];
// packed fp16 activations (tile-major, swizzled)
__device__ __half g_x16  [6389760];     // 65 tiles(128) x 12 ks
__device__ __half g_cat16[10616832];    // 81 tiles(128) x 16 ks
__device__ __half g_ll16 [2097152];     // q: 32t(64)x16ks  / ff: 16t(128)x16ks
__device__ __half g_o16  [2097152];     // 32 tiles(64) x 16 ks
__device__ __half g_h16  [8388608];     // 32 tiles(64) x 64 ks
__device__ __half g_lat16[2097152];     // 32 tiles(64) x 16 ks
__device__ __half g_wtT  [102498304];   // plain transposed [N,K] fp16
__device__ __half g_wt16 [102498304];   // packed swizzled weights

#define OFF_PIN  0
#define OFF_WQ   (OFF_PIN + 768 * 1024)
#define OFF_WKV  (OFF_WQ  + 8 * 1024 * 1024)
#define OFF_WO   (OFF_WKV + 8 * 1024 * 2048)
#define OFF_W1   (OFF_WO  + 8 * 1024 * 1024)
#define OFF_W2   (OFF_W1  + 8 * 1024 * 4096)
#define OFF_POUT (OFF_W2  + 8 * 4096 * 1024)

// ---------------------------------------------------------------------------
// packed half index: row in [0,tiles*bm), col in [0,width).
// layout: [tile][ks][r][64 halves], 16B granules XOR-swizzled by (r&7).
// ---------------------------------------------------------------------------
__device__ __forceinline__ size_t pk_idx(int row, int col, int bm, int width)
{
    int tile = row / bm, r = row % bm;
    int ks = col >> 6, c = col & 63;
    int gh = (c >> 3) ^ (r & 7);
    return (((size_t)tile * (width >> 6) + ks) * bm + r) * 64 + (gh << 3) + (c & 7);
}

__device__ __forceinline__ void pk_store4(__half* out, int row, int col, int bm,
                                          int width, float4 o)
{
    __half2* p = (__half2*)(out + pk_idx(row, col, bm, width));
    p[0] = __floats2half2_rn(o.x, o.y);
    p[1] = __floats2half2_rn(o.z, o.w);
}

// ---------------------------------------------------------------------------
__device__ __forceinline__ void mma_f16(float* d, const uint32_t* a, const uint32_t* b)
{
    asm volatile(
        "mma.sync.aligned.m16n8k16.row.col.f32.f16.f16.f32 "
        "{%0,%1,%2,%3}, {%4,%5,%6,%7}, {%8,%9}, {%0,%1,%2,%3};\n"
        : "+f"(d[0]), "+f"(d[1]), "+f"(d[2]), "+f"(d[3])
        : "r"(a[0]), "r"(a[1]), "r"(a[2]), "r"(a[3]), "r"(b[0]), "r"(b[1]));
}
__device__ __forceinline__ void mbar_init(uint32_t a, uint32_t cnt)
{
    asm volatile("mbarrier.init.shared.b64 [%0], %1;" :: "r"(a), "r"(cnt) : "memory");
}
__device__ __forceinline__ void mbar_expect_tx(uint32_t a, uint32_t bytes)
{
    asm volatile("mbarrier.arrive.expect_tx.shared.b64 _, [%0], %1;"
                 :: "r"(a), "r"(bytes) : "memory");
}
__device__ __forceinline__ void mbar_wait(uint32_t a, uint32_t parity)
{
    asm volatile(
        "{\n\t.reg .pred P;\n\t"
        "LW%=:\n\t"
        "mbarrier.try_wait.parity.acquire.cta.shared::cta.b64 P, [%0], %1, 0x989680;\n\t"
        "@!P bra LW%=;\n\t"
        "}" :: "r"(a), "r"(parity) : "memory");
}
__device__ __forceinline__ void bulk_g2s(uint32_t dst, const void* src,
                                         uint32_t bytes, uint32_t mbar)
{
    asm volatile(
        "cp.async.bulk.shared::cluster.global.mbarrier::complete_tx::bytes "
        "[%0], [%1], %2, [%3];"
        :: "r"(dst), "l"(src), "r"(bytes), "r"(mbar) : "memory");
}

// ---------------------------------------------------------------------------
// fp16 GEMM on packed operands. C[M,N] = A @ Bt^T (+bias)(gelu)(+res).
// BM = NWM*32, BN = 128 (2 warps in N). Apk packed with bm=BM, Bpk bm=128.
// out_mode: 0 = fp32 plain, 1 = fp16 packed (bm=64, width=N).
// ---------------------------------------------------------------------------
template<int NWM, int MINB>
__global__ void __launch_bounds__(NWM * 64, MINB)
hgemm(int M, int N, int K,
      const __half* __restrict__ Apk, const __half* __restrict__ Bpk,
      void* __restrict__ Cv, const float* __restrict__ bias,
      const float* __restrict__ res, int do_gelu, int out_mode)
{
    constexpr int BM = NWM * 32;
    constexpr int A_SB = BM * 128;           // bytes per A stage
    constexpr int STAGE_B = (BM + 128) * 128;
    constexpr int KTB = STAGE_B;

    extern __shared__ char smraw[];
    const uint32_t sb = (uint32_t)__cvta_generic_to_shared(smraw);
    const uint32_t sd = sb + 64;

    const int tid  = threadIdx.x;
    const int wid  = tid >> 5;
    const int lane = tid & 31;
    const int gid  = lane >> 2;
    const int tig  = lane & 3;
    const int bx   = blockIdx.x;
    const int by   = blockIdx.y;

    const int warp_m = (wid % NWM) * 32;
    const int warp_n = (wid / NWM) * 64;

    if (tid == 0) {
#pragma unroll
        for (int s = 0; s < STG; s++) mbar_init(sb + 8 * s, 1);
    }
    __syncthreads();

    const int nk = K >> 6;

    auto fill = [&](int slot, int kt) {
        if (tid == 0) {
            const uint32_t base = sd + (uint32_t)slot * STAGE_B;
            const uint32_t mbar = sb + 8 * slot;
            mbar_expect_tx(mbar, KTB);
            bulk_g2s(base, Apk + ((size_t)by * nk + kt) * (BM * 64), BM * 128, mbar);
            bulk_g2s(base + A_SB, Bpk + ((size_t)bx * nk + kt) * (128 * 64),
                     128 * 128, mbar);
        }
    };

    float acc[2][8][4];
#pragma unroll
    for (int mm = 0; mm < 2; mm++)
#pragma unroll
        for (int nn = 0; nn < 8; nn++)
#pragma unroll
            for (int r = 0; r < 4; r++) acc[mm][nn][r] = 0.0f;

#pragma unroll
    for (int s = 0; s < STG; s++)
        if (s < nk) fill(s, s);

    for (int kt = 0; kt < nk; kt++) {
        const int slot = kt % STG;
        const uint32_t parity = ((uint32_t)(kt / STG)) & 1u;
        mbar_wait(sb + 8 * slot, parity);

        const uint32_t* As32 = (const uint32_t*)(smraw + 64 + (size_t)slot * STAGE_B);
        const uint32_t* Bs32 = As32 + BM * 32;

#pragma unroll
        for (int ks = 0; ks < 4; ks++) {
            const int g0 = ks * 2;
            uint32_t a[2][4], b[8][2];
#pragma unroll
            for (int mm = 0; mm < 2; mm++) {
                int r0 = warp_m + mm * 16 + gid;
                int rs = r0 & 7;
                int o0 = ((g0 ^ rs) << 2) + tig;
                int o1 = (((g0 + 1) ^ rs) << 2) + tig;
                a[mm][0] = As32[r0 * 32 + o0];
                a[mm][1] = As32[(r0 + 8) * 32 + o0];
                a[mm][2] = As32[r0 * 32 + o1];
                a[mm][3] = As32[(r0 + 8) * 32 + o1];
            }
#pragma unroll
            for (int nn = 0; nn < 8; nn++) {
                int c0 = warp_n + nn * 8 + gid;
                int cs = c0 & 7;
                b[nn][0] = Bs32[c0 * 32 + ((g0 ^ cs) << 2) + tig];
                b[nn][1] = Bs32[c0 * 32 + (((g0 + 1) ^ cs) << 2) + tig];
            }
#pragma unroll
            for (int mm = 0; mm < 2; mm++)
#pragma unroll
                for (int nn = 0; nn < 8; nn++)
                    mma_f16(acc[mm][nn], a[mm], b[nn]);
        }

        __syncthreads();
        if (kt + STG < nk) {
            asm volatile("fence.proxy.async.shared::cta;" ::: "memory");
            fill(slot, kt + STG);
        }
    }

    // ---- epilogue ----
    float* Cf = (float*)Cv;
    __half* Ch = (__half*)Cv;
#pragma unroll
    for (int mm = 0; mm < 2; mm++) {
#pragma unroll
        for (int hf = 0; hf < 2; hf++) {
            int row = by * BM + warp_m + mm * 16 + gid + hf * 8;
            if (row >= M) continue;
#pragma unroll
            for (int nn = 0; nn < 8; nn++) {
                int col = bx * 128 + warp_n + nn * 8 + tig * 2;
                float v0 = acc[mm][nn][hf * 2 + 0];
                float v1 = acc[mm][nn][hf * 2 + 1];
                if (bias) { v0 += bias[col]; v1 += bias[col + 1]; }
                if (do_gelu) {
                    v0 = 0.5f * v0 * (1.0f + erff(v0 * 0.70710678118654752f));
                    v1 = 0.5f * v1 * (1.0f + erff(v1 * 0.70710678118654752f));
                }
                if (res) {
                    v0 += res[(size_t)row * N + col];
                    v1 += res[(size_t)row * N + col + 1];
                }
                if (out_mode == 1) {
                    *(__half2*)(Ch + pk_idx(row, col, 64, N)) =
                        __floats2half2_rn(v0, v1);
                } else {
                    Cf[(size_t)row * N + col]     = v0;
                    Cf[(size_t)row * N + col + 1] = v1;
                }
            }
        }
    }
}

#define SMEM_MID   (64 + STG * (128 + 128) * 128)   // 98368
#define SMEM_SMALL (64 + STG * (64 + 128) * 128)    // 73792

// ---------------------------------------------------------------------------
// Weight prep 1: transpose [K,N] fp32 -> plain [N,K] fp16 (coalesced).
// ---------------------------------------------------------------------------
__global__ void transpose_h(const float* __restrict__ in, __half* __restrict__ out,
                            int K, int N)
{
    __shared__ float t[32][33];
    in  += (size_t)blockIdx.z * K * N;
    out += (size_t)blockIdx.z * K * N;
    int x = blockIdx.x * 32 + threadIdx.x;
    int y0 = blockIdx.y * 32;
#pragma unroll
    for (int j = threadIdx.y; j < 32; j += 8)
        t[j][threadIdx.x] = in[(size_t)(y0 + j) * N + x];
    __syncthreads();
    int n0 = blockIdx.x * 32;
#pragma unroll
    for (int j = threadIdx.y; j < 32; j += 8)
        out[(size_t)(n0 + j) * K + y0 + threadIdx.x] = __float2half_rn(t[threadIdx.x][j]);
}

// ---------------------------------------------------------------------------
// Weight prep 2: plain [N,K] fp16 -> packed (bm=128) swizzled. Warp per 128B row.
// ---------------------------------------------------------------------------
__global__ void pack_w(const __half* __restrict__ in, __half* __restrict__ out,
                       int N, int K)
{
    in  += (size_t)blockIdx.z * N * K;
    out += (size_t)blockIdx.z * N * K;
    int gidx = blockIdx.x * blockDim.x + threadIdx.x;
    int warp = gidx >> 5, lane = gidx & 31;
    int nks = K >> 6;
    if (warp >= N * nks) return;
    int n = warp / nks, ks = warp % nks;
    int tile = n >> 7, r = n & 127;
    uint32_t v = ((const uint32_t*)(in + (size_t)n * K + ks * 64))[lane];
    uint32_t* dst = (uint32_t*)(out + (((size_t)tile * nks + ks) * 128 + r) * 64);
    int g = lane >> 2;
    dst[((g ^ (r & 7)) << 2) + (lane & 3)] = v;
}

// fp32 -> packed fp16 (rows x width, pack bm)
__global__ void pack_f32(const float* __restrict__ in, __half* __restrict__ out,
                         int n4, int width, int bm)
{
    int i = blockIdx.x * blockDim.x + threadIdx.x;
    if (i < n4) {
        float4 v = ((const float4*)in)[i];
        int e = i * 4;
        pk_store4(out, e / width, e % width, bm, width, v);
    }
}

// ---------------------------------------------------------------------------
__device__ __forceinline__ float2 block_reduce2(float a, float b)
{
    __shared__ float sa[8], sb_[8];
#pragma unroll
    for (int off = 16; off; off >>= 1) {
        a += __shfl_down_sync(0xFFFFFFFFu, a, off);
        b += __shfl_down_sync(0xFFFFFFFFu, b, off);
    }
    int w = threadIdx.x >> 5, l = threadIdx.x & 31;
    if (l == 0) { sa[w] = a; sb_[w] = b; }
    __syncthreads();
    if (w == 0) {
        a = (l < 8) ? sa[l] : 0.f;
        b = (l < 8) ? sb_[l] : 0.f;
#pragma unroll
        for (int off = 4; off; off >>= 1) {
            a += __shfl_down_sync(0xFFFFFFFFu, a, off);
            b += __shfl_down_sync(0xFFFFFFFFu, b, off);
        }
        if (l == 0) { sa[0] = a; sb_[0] = b; }
    }
    __syncthreads();
    return make_float2(sa[0], sb_[0]);
}

// LayerNorm width=1024. out1: packed fp16 (bm1>0) or fp32 plain (bm1=0),
// with row remap. out2 (optional): packed fp16 bm2 at plain row index.
__global__ __launch_bounds__(256)
void ln_kernel(const float* __restrict__ in, void* __restrict__ out,
               __half* __restrict__ out2,
               const float* __restrict__ g, const float* __restrict__ bta,
               int width, int rpb_in, int rpb_out, int out_off,
               int bm1, int bm2)
{
    int row = blockIdx.x;
    const float* x = in + (size_t)row * width;
    int bi = row / rpb_in, n = row % rpb_in;
    int orow = bi * rpb_out + out_off + n;

    float s = 0.f, s2 = 0.f;
    for (int i = threadIdx.x * 4; i < width; i += blockDim.x * 4) {
        float4 v = *(const float4*)(x + i);
        s  += v.x + v.y + v.z + v.w;
        s2 += v.x * v.x + v.y * v.y + v.z * v.z + v.w * v.w;
    }
    float2 r = block_reduce2(s, s2);
    float mean = r.x / (float)width;
    float var  = r.y / (float)width - mean * mean;
    float rstd = rsqrtf(var + 1e-5f);

    for (int i = threadIdx.x * 4; i < width; i += blockDim.x * 4) {
        float4 v = *(const float4*)(x + i);
        float4 gg = *(const float4*)(g + i);
        float4 bb = *(const float4*)(bta + i);
        float4 o;
        o.x = (v.x - mean) * rstd * gg.x + bb.x;
        o.y = (v.y - mean) * rstd * gg.y + bb.y;
        o.z = (v.z - mean) * rstd * gg.z + bb.z;
        o.w = (v.w - mean) * rstd * gg.w + bb.w;
        if (bm1) {
            pk_store4((__half*)out, orow, i, bm1, width, o);
            if (out2) pk_store4(out2, row, i, bm2, width, o);
        } else {
            *(float4*)((float*)out + (size_t)orow * width + i) = o;
        }
    }
}

__global__ void bcast_kernel(const float* __restrict__ latents, float* __restrict__ lat)
{
    size_t i = (size_t)blockIdx.x * blockDim.x + threadIdx.x;
    size_t tot = (size_t)Bb * NQ * DIM;
    if (i < tot) lat[i] = latents[i % ((size_t)NQ * DIM)];
}

// ---------------------------------------------------------------------------
// Attention: per block (b, h, 16 q-rows). fp32 math, packed fp16 output.
// ---------------------------------------------------------------------------
__global__ __launch_bounds__(256)
void attn_kernel(const float* __restrict__ q,
                 const float* __restrict__ kv,
                 __half* __restrict__ o)
{
    __shared__ float qs[16][DH];
    __shared__ float sc[16][NK];

    int blk = blockIdx.x;
    int qt = blk & 3;
    int h  = (blk >> 2) & 15;
    int b  = blk >> 6;

    const float* qbase = q + ((size_t)b * NQ + qt * 16) * DIM + h * DH;
    for (int i = threadIdx.x; i < 16 * DH; i += 256) {
        int r = i >> 6, c = i & 63;
        qs[r][c] = qbase[(size_t)r * DIM + c];
    }
    __syncthreads();

    const float* kbase = kv + (size_t)b * NK * (2 * DIM) + h * DH;
    const float* vbase = kbase + DIM;

    for (int idx = threadIdx.x; idx < 16 * NK; idx += 256) {
        int r = idx / NK, kk = idx % NK;
        const float* krow = kbase + (size_t)kk * (2 * DIM);
        float acc = 0.f;
#pragma unroll
        for (int d = 0; d < DH; d += 4) {
            float4 k4 = *(const float4*)(krow + d);
            acc += qs[r][d] * k4.x + qs[r][d + 1] * k4.y
                 + qs[r][d + 2] * k4.z + qs[r][d + 3] * k4.w;
        }
        sc[r][kk] = acc * 0.125f;
    }
    __syncthreads();

    int warp = threadIdx.x >> 5, lane = threadIdx.x & 31;
    for (int r = warp * 2; r < warp * 2 + 2; r++) {
        float mx = -1e30f;
        for (int k = lane; k < NK; k += 32) mx = fmaxf(mx, sc[r][k]);
#pragma unroll
        for (int off = 16; off; off >>= 1)
            mx = fmaxf(mx, __shfl_xor_sync(0xFFFFFFFFu, mx, off));
        float sum = 0.f;
        for (int k = lane; k < NK; k += 32) {
            float e = __expf(sc[r][k] - mx);
            sc[r][k] = e;
            sum += e;
        }
#pragma unroll
        for (int off = 16; off; off >>= 1)
            sum += __shfl_xor_sync(0xFFFFFFFFu, sum, off);
        float inv = 1.0f / sum;
        for (int k = lane; k < NK; k += 32) sc[r][k] *= inv;
    }
    __syncthreads();

    int d = threadIdx.x & 63;
    int r0 = threadIdx.x >> 6;
    float acc[4] = {0.f, 0.f, 0.f, 0.f};
    for (int k = 0; k < NK; k++) {
        float vv = vbase[(size_t)k * (2 * DIM) + d];
#pragma unroll
        for (int j = 0; j < 4; j++)
            acc[j] = fmaf(sc[r0 + 4 * j][k], vv, acc[j]);
    }
    int col = h * DH + d;
#pragma unroll
    for (int j = 0; j < 4; j++) {
        int row = b * NQ + qt * 16 + r0 + 4 * j;
        o[pk_idx(row, col, 64, DIM)] = __float2half_rn(acc[j]);
    }
}

// ---------------------------------------------------------------------------
static inline void gemm_mid(const __half* A, const __half* Bt, void* C,
                            int M, int N, int K,
                            const float* bias, const float* res, int gelu, int om)
{
    dim3 grid(N / 128, (M + 127) / 128);
    hgemm<4, 2><<<grid, 256, SMEM_MID>>>(M, N, K, A, Bt, C, bias, res, gelu, om);
}
static inline void gemm_small(const __half* A, const __half* Bt, void* C,
                              int M, int N, int K,
                              const float* bias, const float* res, int gelu, int om)
{
    dim3 grid(N / 128, (M + 63) / 64);
    hgemm<2, 3><<<grid, 128, SMEM_SMALL>>>(M, N, K, A, Bt, C, bias, res, gelu, om);
}
static inline void prep_w(const float* in, __half* wtT, __half* wpk,
                          int K, int N, int layers)
{
    transpose_h<<<dim3(N / 32, K / 32, layers), dim3(32, 8)>>>(in, wtT, K, N);
    int warps = N * (K / 64);
    pack_w<<<dim3((warps * 32 + 255) / 256, 1, layers), 256>>>(wtT, wpk, N, K);
}

extern "C" void kernel_launch(void* const* d_in, const int* in_sizes, int n_in,
                              void* d_out, int out_size)
{
    const float* x          = (const float*)d_in[0];
    const float* latents    = (const float*)d_in[1];
    const float* proj_in_w  = (const float*)d_in[2];
    const float* proj_in_b  = (const float*)d_in[3];
    const float* ln1_g      = (const float*)d_in[4];
    const float* ln1_b      = (const float*)d_in[5];
    const float* ln2_g      = (const float*)d_in[6];
    const float* ln2_b      = (const float*)d_in[7];
    const float* Wq         = (const float*)d_in[8];
    const float* Wkv        = (const float*)d_in[9];
    const float* Wo         = (const float*)d_in[10];
    const float* ff_ln_g    = (const float*)d_in[11];
    const float* ff_ln_b    = (const float*)d_in[12];
    const float* ff_w1      = (const float*)d_in[13];
    const float* ff_w2      = (const float*)d_in[14];
    const float* proj_out_w = (const float*)d_in[15];
    const float* proj_out_b = (const float*)d_in[16];
    const float* norm_out_g = (const float*)d_in[17];
    const float* norm_out_b = (const float*)d_in[18];
    float* out = (float*)d_out;

    cudaFuncSetAttribute((const void*)hgemm<4, 2>,
                         cudaFuncAttributeMaxDynamicSharedMemorySize, SMEM_MID);
    cudaFuncSetAttribute((const void*)hgemm<2, 3>,
                         cudaFuncAttributeMaxDynamicSharedMemorySize, SMEM_SMALL);

    float  *xf, *lat, *qb, *kvb, *tmp;
    __half *x16, *cat16, *ll16, *o16, *h16, *lat16, *wtT, *wpk;
    cudaGetSymbolAddress((void**)&xf,    g_xf);
    cudaGetSymbolAddress((void**)&lat,   g_lat);
    cudaGetSymbolAddress((void**)&qb,    g_q);
    cudaGetSymbolAddress((void**)&kvb,   g_kv);
    cudaGetSymbolAddress((void**)&tmp,   g_tmp);
    cudaGetSymbolAddress((void**)&x16,   g_x16);
    cudaGetSymbolAddress((void**)&cat16, g_cat16);
    cudaGetSymbolAddress((void**)&ll16,  g_ll16);
    cudaGetSymbolAddress((void**)&o16,   g_o16);
    cudaGetSymbolAddress((void**)&h16,   g_h16);
    cudaGetSymbolAddress((void**)&lat16, g_lat16);
    cudaGetSymbolAddress((void**)&wtT,   g_wtT);
    cudaGetSymbolAddress((void**)&wpk,   g_wt16);

    const int Mx = Bb * N1;   // 8224
    const int Ml = Bb * NQ;   // 2048
    const int Mc = Bb * NK;   // 10272

    // ---- prep: proj_in weight + x, then proj_in GEMM early for profiling ----
    prep_w(proj_in_w, wtT + OFF_PIN, wpk + OFF_PIN, EMB, DIM, 1);      // #0,#1
    {
        int n4 = Bb * N1 * EMB / 4;                                     // #2
        pack_f32<<<(n4 + 255) / 256, 256>>>(x, x16, n4, EMB, 128);
    }
    gemm_mid(x16, wpk + OFF_PIN, xf, Mx, DIM, EMB, proj_in_b, nullptr, 0, 0); // #3

    {
        size_t tot = (size_t)Bb * NQ * DIM;
        bcast_kernel<<<(int)((tot + 255) / 256), 256>>>(latents, lat);
    }
    prep_w(Wq,         wtT + OFF_WQ,   wpk + OFF_WQ,   DIM, DIM,     DEPTH);
    prep_w(Wkv,        wtT + OFF_WKV,  wpk + OFF_WKV,  DIM, 2 * DIM, DEPTH);
    prep_w(Wo,         wtT + OFF_WO,   wpk + OFF_WO,   DIM, DIM,     DEPTH);
    prep_w(ff_w1,      wtT + OFF_W1,   wpk + OFF_W1,   DIM, FFI,     DEPTH);
    prep_w(ff_w2,      wtT + OFF_W2,   wpk + OFF_W2,   FFI, DIM,     DEPTH);
    prep_w(proj_out_w, wtT + OFF_POUT, wpk + OFF_POUT, DIM, DIM,     1);

    for (int i = 0; i < DEPTH; i++) {
        const __half* wq  = wpk + OFF_WQ  + (size_t)i * DIM * DIM;
        const __half* wkv = wpk + OFF_WKV + (size_t)i * DIM * 2 * DIM;
        const __half* wo  = wpk + OFF_WO  + (size_t)i * DIM * DIM;
        const __half* w1  = wpk + OFF_W1  + (size_t)i * DIM * FFI;
        const __half* w2  = wpk + OFF_W2  + (size_t)i * FFI * DIM;

        // ln(xf) -> cat16 rows [0,257) per batch  (packed bm=128)
        ln_kernel<<<Mx, 256>>>(xf, cat16, nullptr,
                               ln1_g + (size_t)i * DIM, ln1_b + (size_t)i * DIM,
                               DIM, N1, NK, 0, 128, 0);
        // ln(lat) -> cat16 rows [257,321) (bm=128) AND ll16 (bm=64, for q)
        ln_kernel<<<Ml, 256>>>(lat, cat16, ll16,
                               ln2_g + (size_t)i * DIM, ln2_b + (size_t)i * DIM,
                               DIM, NQ, NK, N1, 128, 64);

        gemm_small(ll16, wq, qb, Ml, DIM, DIM, nullptr, nullptr, 0, 0);       // q fp32
        gemm_mid(cat16, wkv, kvb, Mc, 2 * DIM, DIM, nullptr, nullptr, 0, 0);  // kv fp32

        attn_kernel<<<Bb * HEADS * 4, 256>>>(qb, kvb, o16);   // o16 packed bm=64

        gemm_small(o16, wo, lat, Ml, DIM, DIM, nullptr, lat, 0, 0);           // lat+=oWo

        // ff ln -> ll16 packed bm=128 (feeds mid ff1)
        ln_kernel<<<Ml, 256>>>(lat, ll16, nullptr,
                               ff_ln_g + (size_t)i * DIM, ff_ln_b + (size_t)i * DIM,
                               DIM, NQ, NQ, 0, 128, 0);
        gemm_mid(ll16, w1, h16, Ml, FFI, DIM, nullptr, nullptr, 1, 1);        // gelu->h16
        gemm_small(h16, w2, lat, Ml, DIM, FFI, nullptr, lat, 0, 0);           // lat+=hW2
    }

    {
        int n4 = Bb * NQ * DIM / 4;
        pack_f32<<<(n4 + 255) / 256, 256>>>(lat, lat16, n4, DIM, 64);
    }
    gemm_small(lat16, wpk + OFF_POUT, tmp, Ml, DIM, DIM, proj_out_b, nullptr, 0, 0);
    ln_kernel<<<Ml, 256>>>(tmp, out, nullptr, norm_out_g, norm_out_b,
                           DIM, NQ, NQ, 0, 0, 0);
}

// round 14
// speedup vs baseline: 1.5146x; 1.0190x over previous
#include <cuda_runtime.h>
#include <cuda_fp16.h>
#include <math.h>
#include <stdint.h>

// ---------------------------------------------------------------------------
// ResamplerSD3: 8-layer Perceiver resampler.
// fp16 mma.sync (m16n8k16) GEMMs, fp32 accum. Operands pre-packed into
// stage-contiguous swizzled tiles -> 2 cp.async.bulk per pipeline stage.
// Fragment loads via ldmatrix.x4 (LDSM) on the swizzled layout.
// ---------------------------------------------------------------------------

#define Bb   32
#define N1   257
#define EMB  768
#define DIM  1024
#define HEADS 16
#define DH   64
#define NQ   64
#define FFI  4096
#define NK   (N1 + NQ)        // 321
#define DEPTH 8

#define STG  3
#define BKT  64               // K per stage (64 halves = 128B per packed row)

// ---------------- static device scratch (no allocations allowed) -----------
__device__ float  g_xf   [Bb * N1 * DIM];
__device__ float  g_lat  [Bb * NQ * DIM];
__device__ float  g_q    [Bb * NQ * DIM];
__device__ float  g_kv   [Bb * NK * 2 * DIM];
__device__ float  g_tmp  [Bb * NQ * DIM];
// packed fp16 activations (tile-major, swizzled)
__device__ __half g_x16  [6389760];
__device__ __half g_cat16[10616832];
__device__ __half g_ll16 [2097152];
__device__ __half g_o16  [2097152];
__device__ __half g_h16  [8388608];
__device__ __half g_lat16[2097152];
__device__ __half g_wtT  [102498304];   // plain transposed [N,K] fp16
__device__ __half g_wt16 [102498304];   // packed swizzled weights

#define OFF_PIN  0
#define OFF_WQ   (OFF_PIN + 768 * 1024)
#define OFF_WKV  (OFF_WQ  + 8 * 1024 * 1024)
#define OFF_WO   (OFF_WKV + 8 * 1024 * 2048)
#define OFF_W1   (OFF_WO  + 8 * 1024 * 1024)
#define OFF_W2   (OFF_W1  + 8 * 1024 * 4096)
#define OFF_POUT (OFF_W2  + 8 * 4096 * 1024)

// ---------------------------------------------------------------------------
// packed half index: [tile][ks][r][64 halves], 16B granules XOR-swizzled by r&7
// ---------------------------------------------------------------------------
__device__ __forceinline__ size_t pk_idx(int row, int col, int bm, int width)
{
    int tile = row / bm, r = row % bm;
    int ks = col >> 6, c = col & 63;
    int gh = (c >> 3) ^ (r & 7);
    return (((size_t)tile * (width >> 6) + ks) * bm + r) * 64 + (gh << 3) + (c & 7);
}

__device__ __forceinline__ void pk_store4(__half* out, int row, int col, int bm,
                                          int width, float4 o)
{
    __half2* p = (__half2*)(out + pk_idx(row, col, bm, width));
    p[0] = __floats2half2_rn(o.x, o.y);
    p[1] = __floats2half2_rn(o.z, o.w);
}

// ---------------------------------------------------------------------------
__device__ __forceinline__ void mma_f16(float* d, const uint32_t* a, const uint32_t* b)
{
    asm volatile(
        "mma.sync.aligned.m16n8k16.row.col.f32.f16.f16.f32 "
        "{%0,%1,%2,%3}, {%4,%5,%6,%7}, {%8,%9}, {%0,%1,%2,%3};\n"
        : "+f"(d[0]), "+f"(d[1]), "+f"(d[2]), "+f"(d[3])
        : "r"(a[0]), "r"(a[1]), "r"(a[2]), "r"(a[3]), "r"(b[0]), "r"(b[1]));
}
__device__ __forceinline__ void ldsm_x4(uint32_t& r0, uint32_t& r1,
                                        uint32_t& r2, uint32_t& r3, uint32_t addr)
{
    asm volatile("ldmatrix.sync.aligned.m8n8.x4.shared.b16 {%0,%1,%2,%3}, [%4];"
                 : "=r"(r0), "=r"(r1), "=r"(r2), "=r"(r3) : "r"(addr));
}
__device__ __forceinline__ void mbar_init(uint32_t a, uint32_t cnt)
{
    asm volatile("mbarrier.init.shared.b64 [%0], %1;" :: "r"(a), "r"(cnt) : "memory");
}
__device__ __forceinline__ void mbar_expect_tx(uint32_t a, uint32_t bytes)
{
    asm volatile("mbarrier.arrive.expect_tx.shared.b64 _, [%0], %1;"
                 :: "r"(a), "r"(bytes) : "memory");
}
__device__ __forceinline__ void mbar_wait(uint32_t a, uint32_t parity)
{
    asm volatile(
        "{\n\t.reg .pred P;\n\t"
        "LW%=:\n\t"
        "mbarrier.try_wait.parity.acquire.cta.shared::cta.b64 P, [%0], %1, 0x989680;\n\t"
        "@!P bra LW%=;\n\t"
        "}" :: "r"(a), "r"(parity) : "memory");
}
__device__ __forceinline__ void bulk_g2s(uint32_t dst, const void* src,
                                         uint32_t bytes, uint32_t mbar)
{
    asm volatile(
        "cp.async.bulk.shared::cluster.global.mbarrier::complete_tx::bytes "
        "[%0], [%1], %2, [%3];"
        :: "r"(dst), "l"(src), "r"(bytes), "r"(mbar) : "memory");
}

// ---------------------------------------------------------------------------
// fp16 GEMM on packed operands. C[M,N] = A @ Bt^T (+bias)(gelu)(+res).
// BM = NWM*32, BN = 128. Fragment loads via ldmatrix.x4.
// out_mode: 0 = fp32 plain, 1 = fp16 packed (bm=64, width=N).
// ---------------------------------------------------------------------------
template<int NWM, int MINB>
__global__ void __launch_bounds__(NWM * 64, MINB)
hgemm(int M, int N, int K,
      const __half* __restrict__ Apk, const __half* __restrict__ Bpk,
      void* __restrict__ Cv, const float* __restrict__ bias,
      const float* __restrict__ res, int do_gelu, int out_mode)
{
    constexpr int BM = NWM * 32;
    constexpr int A_SB = BM * 128;           // bytes per A stage
    constexpr int STAGE_B = (BM + 128) * 128;
    constexpr int KTB = STAGE_B;

    extern __shared__ char smraw[];
    const uint32_t sb = (uint32_t)__cvta_generic_to_shared(smraw);
    const uint32_t sd = sb + 64;

    const int tid  = threadIdx.x;
    const int wid  = tid >> 5;
    const int lane = tid & 31;
    const int gid  = lane >> 2;
    const int tig  = lane & 3;
    const int bx   = blockIdx.x;
    const int by   = blockIdx.y;

    const int warp_m = (wid % NWM) * 32;
    const int warp_n = (wid / NWM) * 64;

    // ldmatrix per-lane address components (swizzle rs == lr for all tiles)
    const int quad = lane >> 3;
    const int lr   = lane & 7;
    const uint32_t aRow = (uint32_t)(warp_m + ((quad & 1) << 3) + lr) * 128u;
    const int aG = quad >> 1;
    const uint32_t bRow = (uint32_t)(warp_n + ((quad >> 1) << 3) + lr) * 128u;
    const int bG = quad & 1;

    if (tid == 0) {
#pragma unroll
        for (int s = 0; s < STG; s++) mbar_init(sb + 8 * s, 1);
    }
    __syncthreads();

    const int nk = K >> 6;

    auto fill = [&](int slot, int kt) {
        if (tid == 0) {
            const uint32_t base = sd + (uint32_t)slot * STAGE_B;
            const uint32_t mbar = sb + 8 * slot;
            mbar_expect_tx(mbar, KTB);
            bulk_g2s(base, Apk + ((size_t)by * nk + kt) * (BM * 64), BM * 128, mbar);
            bulk_g2s(base + A_SB, Bpk + ((size_t)bx * nk + kt) * (128 * 64),
                     128 * 128, mbar);
        }
    };

    float acc[2][8][4];
#pragma unroll
    for (int mm = 0; mm < 2; mm++)
#pragma unroll
        for (int nn = 0; nn < 8; nn++)
#pragma unroll
            for (int r = 0; r < 4; r++) acc[mm][nn][r] = 0.0f;

#pragma unroll
    for (int s = 0; s < STG; s++)
        if (s < nk) fill(s, s);

    for (int kt = 0; kt < nk; kt++) {
        const int slot = kt % STG;
        const uint32_t parity = ((uint32_t)(kt / STG)) & 1u;
        mbar_wait(sb + 8 * slot, parity);

        const uint32_t sA = sd + (uint32_t)slot * STAGE_B;
        const uint32_t sB = sA + A_SB;

#pragma unroll
        for (int ks = 0; ks < 4; ks++) {
            const int g2 = ks * 2;
            const uint32_t aSw = (uint32_t)(((g2 + aG) ^ lr) << 4);
            const uint32_t bSw = (uint32_t)(((g2 + bG) ^ lr) << 4);

            uint32_t a[2][4], b[8][2];
#pragma unroll
            for (int mm = 0; mm < 2; mm++)
                ldsm_x4(a[mm][0], a[mm][1], a[mm][2], a[mm][3],
                        sA + aRow + (uint32_t)(mm * 2048) + aSw);
#pragma unroll
            for (int p = 0; p < 4; p++)
                ldsm_x4(b[2 * p][0], b[2 * p][1], b[2 * p + 1][0], b[2 * p + 1][1],
                        sB + bRow + (uint32_t)(p * 2048) + bSw);

#pragma unroll
            for (int mm = 0; mm < 2; mm++)
#pragma unroll
                for (int nn = 0; nn < 8; nn++)
                    mma_f16(acc[mm][nn], a[mm], b[nn]);
        }

        __syncthreads();
        if (kt + STG < nk) {
            asm volatile("fence.proxy.async.shared::cta;" ::: "memory");
            fill(slot, kt + STG);
        }
    }

    // ---- epilogue ----
    float* Cf = (float*)Cv;
    __half* Ch = (__half*)Cv;
#pragma unroll
    for (int mm = 0; mm < 2; mm++) {
#pragma unroll
        for (int hf = 0; hf < 2; hf++) {
            int row = by * BM + warp_m + mm * 16 + gid + hf * 8;
            if (row >= M) continue;
#pragma unroll
            for (int nn = 0; nn < 8; nn++) {
                int col = bx * 128 + warp_n + nn * 8 + tig * 2;
                float v0 = acc[mm][nn][hf * 2 + 0];
                float v1 = acc[mm][nn][hf * 2 + 1];
                if (bias) { v0 += bias[col]; v1 += bias[col + 1]; }
                if (do_gelu) {
                    v0 = 0.5f * v0 * (1.0f + erff(v0 * 0.70710678118654752f));
                    v1 = 0.5f * v1 * (1.0f + erff(v1 * 0.70710678118654752f));
                }
                if (res) {
                    v0 += res[(size_t)row * N + col];
                    v1 += res[(size_t)row * N + col + 1];
                }
                if (out_mode == 1) {
                    *(__half2*)(Ch + pk_idx(row, col, 64, N)) =
                        __floats2half2_rn(v0, v1);
                } else {
                    Cf[(size_t)row * N + col]     = v0;
                    Cf[(size_t)row * N + col + 1] = v1;
                }
            }
        }
    }
}

#define SMEM_MID   (64 + STG * (128 + 128) * 128)   // 98368
#define SMEM_SMALL (64 + STG * (64 + 128) * 128)    // 73792

// ---------------------------------------------------------------------------
__global__ void transpose_h(const float* __restrict__ in, __half* __restrict__ out,
                            int K, int N)
{
    __shared__ float t[32][33];
    in  += (size_t)blockIdx.z * K * N;
    out += (size_t)blockIdx.z * K * N;
    int x = blockIdx.x * 32 + threadIdx.x;
    int y0 = blockIdx.y * 32;
#pragma unroll
    for (int j = threadIdx.y; j < 32; j += 8)
        t[j][threadIdx.x] = in[(size_t)(y0 + j) * N + x];
    __syncthreads();
    int n0 = blockIdx.x * 32;
#pragma unroll
    for (int j = threadIdx.y; j < 32; j += 8)
        out[(size_t)(n0 + j) * K + y0 + threadIdx.x] = __float2half_rn(t[threadIdx.x][j]);
}

__global__ void pack_w(const __half* __restrict__ in, __half* __restrict__ out,
                       int N, int K)
{
    in  += (size_t)blockIdx.z * N * K;
    out += (size_t)blockIdx.z * N * K;
    int gidx = blockIdx.x * blockDim.x + threadIdx.x;
    int warp = gidx >> 5, lane = gidx & 31;
    int nks = K >> 6;
    if (warp >= N * nks) return;
    int n = warp / nks, ks = warp % nks;
    int tile = n >> 7, r = n & 127;
    uint32_t v = ((const uint32_t*)(in + (size_t)n * K + ks * 64))[lane];
    uint32_t* dst = (uint32_t*)(out + (((size_t)tile * nks + ks) * 128 + r) * 64);
    int g = lane >> 2;
    dst[((g ^ (r & 7)) << 2) + (lane & 3)] = v;
}

__global__ void pack_f32(const float* __restrict__ in, __half* __restrict__ out,
                         int n4, int width, int bm)
{
    int i = blockIdx.x * blockDim.x + threadIdx.x;
    if (i < n4) {
        float4 v = ((const float4*)in)[i];
        int e = i * 4;
        pk_store4(out, e / width, e % width, bm, width, v);
    }
}

// ---------------------------------------------------------------------------
__device__ __forceinline__ float2 block_reduce2(float a, float b)
{
    __shared__ float sa[8], sb_[8];
#pragma unroll
    for (int off = 16; off; off >>= 1) {
        a += __shfl_down_sync(0xFFFFFFFFu, a, off);
        b += __shfl_down_sync(0xFFFFFFFFu, b, off);
    }
    int w = threadIdx.x >> 5, l = threadIdx.x & 31;
    if (l == 0) { sa[w] = a; sb_[w] = b; }
    __syncthreads();
    if (w == 0) {
        a = (l < 8) ? sa[l] : 0.f;
        b = (l < 8) ? sb_[l] : 0.f;
#pragma unroll
        for (int off = 4; off; off >>= 1) {
            a += __shfl_down_sync(0xFFFFFFFFu, a, off);
            b += __shfl_down_sync(0xFFFFFFFFu, b, off);
        }
        if (l == 0) { sa[0] = a; sb_[0] = b; }
    }
    __syncthreads();
    return make_float2(sa[0], sb_[0]);
}

__global__ __launch_bounds__(256)
void ln_kernel(const float* __restrict__ in, void* __restrict__ out,
               __half* __restrict__ out2,
               const float* __restrict__ g, const float* __restrict__ bta,
               int width, int rpb_in, int rpb_out, int out_off,
               int bm1, int bm2)
{
    int row = blockIdx.x;
    const float* x = in + (size_t)row * width;
    int bi = row / rpb_in, n = row % rpb_in;
    int orow = bi * rpb_out + out_off + n;

    float s = 0.f, s2 = 0.f;
    for (int i = threadIdx.x * 4; i < width; i += blockDim.x * 4) {
        float4 v = *(const float4*)(x + i);
        s  += v.x + v.y + v.z + v.w;
        s2 += v.x * v.x + v.y * v.y + v.z * v.z + v.w * v.w;
    }
    float2 r = block_reduce2(s, s2);
    float mean = r.x / (float)width;
    float var  = r.y / (float)width - mean * mean;
    float rstd = rsqrtf(var + 1e-5f);

    for (int i = threadIdx.x * 4; i < width; i += blockDim.x * 4) {
        float4 v = *(const float4*)(x + i);
        float4 gg = *(const float4*)(g + i);
        float4 bb = *(const float4*)(bta + i);
        float4 o;
        o.x = (v.x - mean) * rstd * gg.x + bb.x;
        o.y = (v.y - mean) * rstd * gg.y + bb.y;
        o.z = (v.z - mean) * rstd * gg.z + bb.z;
        o.w = (v.w - mean) * rstd * gg.w + bb.w;
        if (bm1) {
            pk_store4((__half*)out, orow, i, bm1, width, o);
            if (out2) pk_store4(out2, row, i, bm2, width, o);
        } else {
            *(float4*)((float*)out + (size_t)orow * width + i) = o;
        }
    }
}

__global__ void bcast_kernel(const float* __restrict__ latents, float* __restrict__ lat)
{
    size_t i = (size_t)blockIdx.x * blockDim.x + threadIdx.x;
    size_t tot = (size_t)Bb * NQ * DIM;
    if (i < tot) lat[i] = latents[i % ((size_t)NQ * DIM)];
}

// ---------------------------------------------------------------------------
__global__ __launch_bounds__(256)
void attn_kernel(const float* __restrict__ q,
                 const float* __restrict__ kv,
                 __half* __restrict__ o)
{
    __shared__ float qs[16][DH];
    __shared__ float sc[16][NK];

    int blk = blockIdx.x;
    int qt = blk & 3;
    int h  = (blk >> 2) & 15;
    int b  = blk >> 6;

    const float* qbase = q + ((size_t)b * NQ + qt * 16) * DIM + h * DH;
    for (int i = threadIdx.x; i < 16 * DH; i += 256) {
        int r = i >> 6, c = i & 63;
        qs[r][c] = qbase[(size_t)r * DIM + c];
    }
    __syncthreads();

    const float* kbase = kv + (size_t)b * NK * (2 * DIM) + h * DH;
    const float* vbase = kbase + DIM;

    for (int idx = threadIdx.x; idx < 16 * NK; idx += 256) {
        int r = idx / NK, kk = idx % NK;
        const float* krow = kbase + (size_t)kk * (2 * DIM);
        float acc = 0.f;
#pragma unroll
        for (int d = 0; d < DH; d += 4) {
            float4 k4 = *(const float4*)(krow + d);
            acc += qs[r][d] * k4.x + qs[r][d + 1] * k4.y
                 + qs[r][d + 2] * k4.z + qs[r][d + 3] * k4.w;
        }
        sc[r][kk] = acc * 0.125f;
    }
    __syncthreads();

    int warp = threadIdx.x >> 5, lane = threadIdx.x & 31;
    for (int r = warp * 2; r < warp * 2 + 2; r++) {
        float mx = -1e30f;
        for (int k = lane; k < NK; k += 32) mx = fmaxf(mx, sc[r][k]);
#pragma unroll
        for (int off = 16; off; off >>= 1)
            mx = fmaxf(mx, __shfl_xor_sync(0xFFFFFFFFu, mx, off));
        float sum = 0.f;
        for (int k = lane; k < NK; k += 32) {
            float e = __expf(sc[r][k] - mx);
            sc[r][k] = e;
            sum += e;
        }
#pragma unroll
        for (int off = 16; off; off >>= 1)
            sum += __shfl_xor_sync(0xFFFFFFFFu, sum, off);
        float inv = 1.0f / sum;
        for (int k = lane; k < NK; k += 32) sc[r][k] *= inv;
    }
    __syncthreads();

    int d = threadIdx.x & 63;
    int r0 = threadIdx.x >> 6;
    float acc[4] = {0.f, 0.f, 0.f, 0.f};
    for (int k = 0; k < NK; k++) {
        float vv = vbase[(size_t)k * (2 * DIM) + d];
#pragma unroll
        for (int j = 0; j < 4; j++)
            acc[j] = fmaf(sc[r0 + 4 * j][k], vv, acc[j]);
    }
    int col = h * DH + d;
#pragma unroll
    for (int j = 0; j < 4; j++) {
        int row = b * NQ + qt * 16 + r0 + 4 * j;
        o[pk_idx(row, col, 64, DIM)] = __float2half_rn(acc[j]);
    }
}

// ---------------------------------------------------------------------------
static inline void gemm_mid(const __half* A, const __half* Bt, void* C,
                            int M, int N, int K,
                            const float* bias, const float* res, int gelu, int om)
{
    dim3 grid(N / 128, (M + 127) / 128);
    hgemm<4, 2><<<grid, 256, SMEM_MID>>>(M, N, K, A, Bt, C, bias, res, gelu, om);
}
static inline void gemm_small(const __half* A, const __half* Bt, void* C,
                              int M, int N, int K,
                              const float* bias, const float* res, int gelu, int om)
{
    dim3 grid(N / 128, (M + 63) / 64);
    hgemm<2, 3><<<grid, 128, SMEM_SMALL>>>(M, N, K, A, Bt, C, bias, res, gelu, om);
}
static inline void prep_w(const float* in, __half* wtT, __half* wpk,
                          int K, int N, int layers)
{
    transpose_h<<<dim3(N / 32, K / 32, layers), dim3(32, 8)>>>(in, wtT, K, N);
    int warps = N * (K / 64);
    pack_w<<<dim3((warps * 32 + 255) / 256, 1, layers), 256>>>(wtT, wpk, N, K);
}

extern "C" void kernel_launch(void* const* d_in, const int* in_sizes, int n_in,
                              void* d_out, int out_size)
{
    const float* x          = (const float*)d_in[0];
    const float* latents    = (const float*)d_in[1];
    const float* proj_in_w  = (const float*)d_in[2];
    const float* proj_in_b  = (const float*)d_in[3];
    const float* ln1_g      = (const float*)d_in[4];
    const float* ln1_b      = (const float*)d_in[5];
    const float* ln2_g      = (const float*)d_in[6];
    const float* ln2_b      = (const float*)d_in[7];
    const float* Wq         = (const float*)d_in[8];
    const float* Wkv        = (const float*)d_in[9];
    const float* Wo         = (const float*)d_in[10];
    const float* ff_ln_g    = (const float*)d_in[11];
    const float* ff_ln_b    = (const float*)d_in[12];
    const float* ff_w1      = (const float*)d_in[13];
    const float* ff_w2      = (const float*)d_in[14];
    const float* proj_out_w = (const float*)d_in[15];
    const float* proj_out_b = (const float*)d_in[16];
    const float* norm_out_g = (const float*)d_in[17];
    const float* norm_out_b = (const float*)d_in[18];
    float* out = (float*)d_out;

    cudaFuncSetAttribute((const void*)hgemm<4, 2>,
                         cudaFuncAttributeMaxDynamicSharedMemorySize, SMEM_MID);
    cudaFuncSetAttribute((const void*)hgemm<2, 3>,
                         cudaFuncAttributeMaxDynamicSharedMemorySize, SMEM_SMALL);

    float  *xf, *lat, *qb, *kvb, *tmp;
    __half *x16, *cat16, *ll16, *o16, *h16, *lat16, *wtT, *wpk;
    cudaGetSymbolAddress((void**)&xf,    g_xf);
    cudaGetSymbolAddress((void**)&lat,   g_lat);
    cudaGetSymbolAddress((void**)&qb,    g_q);
    cudaGetSymbolAddress((void**)&kvb,   g_kv);
    cudaGetSymbolAddress((void**)&tmp,   g_tmp);
    cudaGetSymbolAddress((void**)&x16,   g_x16);
    cudaGetSymbolAddress((void**)&cat16, g_cat16);
    cudaGetSymbolAddress((void**)&ll16,  g_ll16);
    cudaGetSymbolAddress((void**)&o16,   g_o16);
    cudaGetSymbolAddress((void**)&h16,   g_h16);
    cudaGetSymbolAddress((void**)&lat16, g_lat16);
    cudaGetSymbolAddress((void**)&wtT,   g_wtT);
    cudaGetSymbolAddress((void**)&wpk,   g_wt16);

    const int Mx = Bb * N1;   // 8224
    const int Ml = Bb * NQ;   // 2048
    const int Mc = Bb * NK;   // 10272

    // ---- prep: proj_in weight + x, then proj_in GEMM early for profiling ----
    prep_w(proj_in_w, wtT + OFF_PIN, wpk + OFF_PIN, EMB, DIM, 1);      // #0,#1
    {
        int n4 = Bb * N1 * EMB / 4;                                     // #2
        pack_f32<<<(n4 + 255) / 256, 256>>>(x, x16, n4, EMB, 128);
    }
    gemm_mid(x16, wpk + OFF_PIN, xf, Mx, DIM, EMB, proj_in_b, nullptr, 0, 0); // #3

    {
        size_t tot = (size_t)Bb * NQ * DIM;
        bcast_kernel<<<(int)((tot + 255) / 256), 256>>>(latents, lat);
    }
    prep_w(Wq,         wtT + OFF_WQ,   wpk + OFF_WQ,   DIM, DIM,     DEPTH);
    prep_w(Wkv,        wtT + OFF_WKV,  wpk + OFF_WKV,  DIM, 2 * DIM, DEPTH);
    prep_w(Wo,         wtT + OFF_WO,   wpk + OFF_WO,   DIM, DIM,     DEPTH);
    prep_w(ff_w1,      wtT + OFF_W1,   wpk + OFF_W1,   DIM, FFI,     DEPTH);
    prep_w(ff_w2,      wtT + OFF_W2,   wpk + OFF_W2,   FFI, DIM,     DEPTH);
    prep_w(proj_out_w, wtT + OFF_POUT, wpk + OFF_POUT, DIM, DIM,     1);

    for (int i = 0; i < DEPTH; i++) {
        const __half* wq  = wpk + OFF_WQ  + (size_t)i * DIM * DIM;
        const __half* wkv = wpk + OFF_WKV + (size_t)i * DIM * 2 * DIM;
        const __half* wo  = wpk + OFF_WO  + (size_t)i * DIM * DIM;
        const __half* w1  = wpk + OFF_W1  + (size_t)i * DIM * FFI;
        const __half* w2  = wpk + OFF_W2  + (size_t)i * FFI * DIM;

        // ln(xf) -> cat16 rows [0,257) per batch  (packed bm=128)
        ln_kernel<<<Mx, 256>>>(xf, cat16, nullptr,
                               ln1_g + (size_t)i * DIM, ln1_b + (size_t)i * DIM,
                               DIM, N1, NK, 0, 128, 0);
        // ln(lat) -> cat16 rows [257,321) (bm=128) AND ll16 (bm=64, for q)
        ln_kernel<<<Ml, 256>>>(lat, cat16, ll16,
                               ln2_g + (size_t)i * DIM, ln2_b + (size_t)i * DIM,
                               DIM, NQ, NK, N1, 128, 64);

        gemm_small(ll16, wq, qb, Ml, DIM, DIM, nullptr, nullptr, 0, 0);       // q fp32
        gemm_mid(cat16, wkv, kvb, Mc, 2 * DIM, DIM, nullptr, nullptr, 0, 0);  // kv fp32

        attn_kernel<<<Bb * HEADS * 4, 256>>>(qb, kvb, o16);   // o16 packed bm=64

        gemm_small(o16, wo, lat, Ml, DIM, DIM, nullptr, lat, 0, 0);           // lat+=oWo

        // ff ln -> ll16 packed bm=128 (feeds mid ff1)
        ln_kernel<<<Ml, 256>>>(lat, ll16, nullptr,
                               ff_ln_g + (size_t)i * DIM, ff_ln_b + (size_t)i * DIM,
                               DIM, NQ, NQ, 0, 128, 0);
        gemm_mid(ll16, w1, h16, Ml, FFI, DIM, nullptr, nullptr, 1, 1);        // gelu->h16
        gemm_small(h16, w2, lat, Ml, DIM, FFI, nullptr, lat, 0, 0);           // lat+=hW2
    }

    {
        int n4 = Bb * NQ * DIM / 4;
        pack_f32<<<(n4 + 255) / 256, 256>>>(lat, lat16, n4, DIM, 64);
    }
    gemm_small(lat16, wpk + OFF_POUT, tmp, Ml, DIM, DIM, proj_out_b, nullptr, 0, 0);
    ln_kernel<<<Ml, 256>>>(tmp, out, nullptr, norm_out_g, norm_out_b,
                           DIM, NQ, NQ, 0, 0, 0);
}